// round 3
// baseline (speedup 1.0000x reference)
#include <cuda_runtime.h>

#define Dd 48
#define Hh 256
#define Ww 256
#define DMk 48
#define HMk 128
#define WMk 128
#define PHn 4
#define HALFW (Ww / 2)                 // 128 == blockDim.x of warp kernel
#define CS (Dd * Hh * Ww * 2)          // 6,291,456 floats per phase slab
#define NPIX (Dd * Hh * Ww)            // 3,145,728 pixels
#define MVF_CH (DMk * HMk * WMk)       // 786,432 floats per mvf channel

// 50.3 MB scratch: imgPair[i] = (img[i].c0, img[i].c1, img[i+1].c0, img[i+1].c1)
// (x+1 clamped within the row). Gives 16B-aligned x-pair fetches for the gather.
__device__ float4 g_imgPair[NPIX];

// ---------------------------------------------------------------------------
// Prep: build imgPair AND write the passthrough slab out[:,0] = image.
// Reads image once (25 MB), writes 50 MB scratch + 25 MB out. Pure streaming.
// ---------------------------------------------------------------------------
__global__ void __launch_bounds__(256)
prep_kernel(const float2* __restrict__ img2, float2* __restrict__ out2) {
    int i = blockIdx.x * blockDim.x + threadIdx.x;
    if (i >= NPIX) return;
    int x = i & (Ww - 1);
    float2 a = __ldg(img2 + i);
    float2 b = __ldg(img2 + i + (x < Ww - 1 ? 1 : 0));
    g_imgPair[i] = make_float4(a.x, a.y, b.x, b.y);
    out2[i] = a;
}

// ---------------------------------------------------------------------------
// Trilinear sample via the pair scratch: 4 x LDG.128 per sample instead of
// 8 x LDG.64. Validity folded into per-axis weights; indices clamped.
// ---------------------------------------------------------------------------
__device__ __forceinline__ float2 sample3d_pair(float cz, float cy, float cx) {
    float zf = floorf(cz), yf = floorf(cy), xf = floorf(cx);
    float fz = cz - zf, fy = cy - yf, fx = cx - xf;
    int z0 = (int)zf, y0 = (int)yf, x0 = (int)xf;
    int z1 = z0 + 1, y1 = y0 + 1;

    float wz[2], wy[2];
    wz[0] = (1.f - fz) * (((unsigned)z0 < (unsigned)Dd) ? 1.f : 0.f);
    wz[1] = fz         * (((unsigned)z1 < (unsigned)Dd) ? 1.f : 0.f);
    wy[0] = (1.f - fy) * (((unsigned)y0 < (unsigned)Hh) ? 1.f : 0.f);
    wy[1] = fy         * (((unsigned)y1 < (unsigned)Hh) ? 1.f : 0.f);
    float wx0 = (1.f - fx) * (((unsigned)x0       < (unsigned)Ww) ? 1.f : 0.f);
    float wx1 = fx         * (((unsigned)(x0 + 1) < (unsigned)Ww) ? 1.f : 0.f);

    int zi[2] = {min(max(z0, 0), Dd - 1), min(max(z1, 0), Dd - 1)};
    int yi[2] = {min(max(y0, 0), Hh - 1), min(max(y1, 0), Hh - 1)};
    int xc0   = min(max(x0, 0), Ww - 1);
    bool hiOK = (x0 >= 0);   // x0 < 0: both x-taps resolve to img[0] (lo)

    float ax = 0.f, ay = 0.f;
#pragma unroll
    for (int a = 0; a < 2; a++) {
#pragma unroll
        for (int b = 0; b < 2; b++) {
            float wzy = wz[a] * wy[b];
            const float4 v = __ldg(&g_imgPair[(zi[a] * Hh + yi[b]) * Ww + xc0]);
            float c1x = hiOK ? v.z : v.x;
            float c1y = hiOK ? v.w : v.y;
            ax = fmaf(wzy, fmaf(wx0, v.x, wx1 * c1x), ax);
            ay = fmaf(wzy, fmaf(wx0, v.y, wx1 * c1y), ay);
        }
    }
    return make_float2(ax, ay);
}

// ---------------------------------------------------------------------------
// Fused: on-the-fly 2x linear upsample of mvf (H,W dims; D identity; jax
// half-pixel convention, edge-clamp == JAX renormalization), flow scale
// (1,2,2), grid-sample, channel-last float4 store.
//
// Block = 128 threads = one output row-pair span; grid = (Hh, Dd, PHn).
// y-interp of mvf is block-uniform -> staged through shared memory.
// ---------------------------------------------------------------------------
__global__ void __launch_bounds__(128)
warp_kernel(const float* __restrict__ mvf, float* __restrict__ out) {
    __shared__ float ymix[3][WMk];

    int tx = threadIdx.x;      // 0..127
    int y  = blockIdx.x;       // 0..255
    int z  = blockIdx.y;       // 0..47
    int ph = blockIdx.z;       // 0..3

    // y-dim resize taps (uniform across block)
    int  yk   = y >> 1;
    bool yodd = (y & 1) != 0;
    int  ya   = yodd ? yk : (yk > 0 ? yk - 1 : 0);
    int  yb   = yodd ? (yk < HMk - 1 ? yk + 1 : HMk - 1) : yk;
    float wa  = yodd ? 0.75f : 0.25f;
    float wb  = 1.f - wa;

    const float* mbase = mvf + (size_t)ph * 3 * MVF_CH + (size_t)z * HMk * WMk;
#pragma unroll
    for (int c = 0; c < 3; c++) {
        const float* rowa = mbase + (size_t)c * MVF_CH + ya * WMk;
        const float* rowb = mbase + (size_t)c * MVF_CH + yb * WMk;
        ymix[c][tx] = fmaf(wa, __ldg(rowa + tx), wb * __ldg(rowb + tx));
    }
    __syncthreads();

    int xlo = (tx > 0) ? tx - 1 : 0;
    int xhi = (tx < WMk - 1) ? tx + 1 : WMk - 1;

    float v_even[3], v_odd[3];
#pragma unroll
    for (int c = 0; c < 3; c++) {
        float lo = ymix[c][xlo], mid = ymix[c][tx], hi = ymix[c][xhi];
        v_even[c] = fmaf(0.25f, lo,  0.75f * mid);
        v_odd[c]  = fmaf(0.75f, mid, 0.25f * hi);
    }

    int x0 = 2 * tx;
    // flow scale (1, 2, 2); coords are absolute voxel coordinates
    float2 r0 = sample3d_pair((float)z + v_even[0],
                              (float)y + 2.f * v_even[1],
                              (float)x0 + 2.f * v_even[2]);
    float2 r1 = sample3d_pair((float)z + v_odd[0],
                              (float)y + 2.f * v_odd[1],
                              (float)(x0 + 1) + 2.f * v_odd[2]);

    float4* o4 = (float4*)(out + (size_t)(1 + ph) * CS);
    o4[(z * Hh + y) * HALFW + tx] = make_float4(r0.x, r0.y, r1.x, r1.y);
}

// ---------------------------------------------------------------------------
extern "C" void kernel_launch(void* const* d_in, const int* in_sizes, int n_in,
                              void* d_out, int out_size) {
    const float* image = (const float*)d_in[0];   // (1,1,48,256,256,2) f32
    const float* mvf   = (const float*)d_in[1];   // (1,4,3,48,128,128) f32
    float* out = (float*)d_out;                   // (1,5,48,256,256,2) f32

    prep_kernel<<<(NPIX + 255) / 256, 256>>>((const float2*)image,
                                             (float2*)out);

    dim3 grid(Hh, Dd, PHn);
    warp_kernel<<<grid, 128>>>(mvf, out);
}

// round 4
// speedup vs baseline: 1.2373x; 1.2373x over previous
#include <cuda_runtime.h>

#define Dd 48
#define Hh 256
#define Ww 256
#define DMk 48
#define HMk 128
#define WMk 128
#define PHn 4
#define CS (Dd * Hh * Ww * 2)          // 6,291,456 floats per phase slab
#define NPIX (Dd * Hh * Ww)            // 3,145,728 pixels
#define MVF_CH (DMk * HMk * WMk)       // 786,432 floats per mvf channel

// ---------------------------------------------------------------------------
// Passthrough: out[:, 0] = image  (float4 vectorized copy)
// ---------------------------------------------------------------------------
__global__ void copy_image_kernel(const float4* __restrict__ src,
                                  float4* __restrict__ dst) {
    int i = blockIdx.x * blockDim.x + threadIdx.x;
    if (i < CS / 4) dst[i] = src[i];
}

// ---------------------------------------------------------------------------
// Trilinear grid-sample (zeros padding, absolute voxel coords) of the
// 2-channel channel-last image. Validity folded into per-axis weights;
// indices clamped so dead loads stay in bounds.
// ---------------------------------------------------------------------------
__device__ __forceinline__ float2 sample3d(const float2* __restrict__ img,
                                           float cz, float cy, float cx) {
    float zf = floorf(cz), yf = floorf(cy), xf = floorf(cx);
    float fz = cz - zf, fy = cy - yf, fx = cx - xf;
    int z0 = (int)zf, y0 = (int)yf, x0 = (int)xf;
    int z1 = z0 + 1, y1 = y0 + 1, x1 = x0 + 1;

    float wz[2], wy[2], wx[2];
    wz[0] = (1.f - fz) * (((unsigned)z0 < (unsigned)Dd) ? 1.f : 0.f);
    wz[1] = fz         * (((unsigned)z1 < (unsigned)Dd) ? 1.f : 0.f);
    wy[0] = (1.f - fy) * (((unsigned)y0 < (unsigned)Hh) ? 1.f : 0.f);
    wy[1] = fy         * (((unsigned)y1 < (unsigned)Hh) ? 1.f : 0.f);
    wx[0] = (1.f - fx) * (((unsigned)x0 < (unsigned)Ww) ? 1.f : 0.f);
    wx[1] = fx         * (((unsigned)x1 < (unsigned)Ww) ? 1.f : 0.f);

    int zi[2] = {min(max(z0, 0), Dd - 1), min(max(z1, 0), Dd - 1)};
    int yi[2] = {min(max(y0, 0), Hh - 1), min(max(y1, 0), Hh - 1)};
    int xi[2] = {min(max(x0, 0), Ww - 1), min(max(x1, 0), Ww - 1)};

    float ax = 0.f, ay = 0.f;
#pragma unroll
    for (int a = 0; a < 2; a++) {
#pragma unroll
        for (int b = 0; b < 2; b++) {
            float wzy = wz[a] * wy[b];
            int rb = (zi[a] * Hh + yi[b]) * Ww;
#pragma unroll
            for (int c = 0; c < 2; c++) {
                float w = wzy * wx[c];
                float2 v = __ldg(img + rb + xi[c]);
                ax = fmaf(w, v.x, ax);
                ay = fmaf(w, v.y, ay);
            }
        }
    }
    return make_float2(ax, ay);
}

// ---------------------------------------------------------------------------
// Fused warp: one thread per OUTPUT PIXEL (8B lane stride -> warp gather
// footprint ~256B = 8 sectors per LDG, half of the x-pair layout).
// Block = 256 threads = one full output x-row; grid = (Hh, Dd, PHn).
// mvf y-interp (block-uniform taps) staged in SMEM; per-thread x-interp.
// ---------------------------------------------------------------------------
__global__ void __launch_bounds__(256)
warp_kernel(const float* __restrict__ image,
            const float* __restrict__ mvf,
            float* __restrict__ out) {
    __shared__ float ymix[3][WMk];

    int tx = threadIdx.x;      // 0..255 = output x
    int y  = blockIdx.x;       // 0..255
    int z  = blockIdx.y;       // 0..47
    int ph = blockIdx.z;       // 0..3

    // y-dim resize taps (uniform across block):
    // out[2k] = .25*in[k-1] + .75*in[k]; out[2k+1] = .75*in[k] + .25*in[k+1]
    int  yk   = y >> 1;
    bool yodd = (y & 1) != 0;
    int  ya   = yodd ? yk : (yk > 0 ? yk - 1 : 0);
    int  yb   = yodd ? (yk < HMk - 1 ? yk + 1 : HMk - 1) : yk;
    float wya = yodd ? 0.75f : 0.25f;
    float wyb = 1.f - wya;

    const float* mbase = mvf + (size_t)ph * 3 * MVF_CH + (size_t)z * HMk * WMk;
    if (tx < WMk) {
#pragma unroll
        for (int c = 0; c < 3; c++) {
            const float* rowa = mbase + (size_t)c * MVF_CH + ya * WMk;
            const float* rowb = mbase + (size_t)c * MVF_CH + yb * WMk;
            ymix[c][tx] = fmaf(wya, __ldg(rowa + tx), wyb * __ldg(rowb + tx));
        }
    }
    __syncthreads();

    // x-dim resize taps for this output x = tx
    int  k    = tx >> 1;
    bool xodd = (tx & 1) != 0;
    int  xa   = xodd ? k : (k > 0 ? k - 1 : 0);
    int  xb   = xodd ? (k < WMk - 1 ? k + 1 : WMk - 1) : k;
    float wxa = xodd ? 0.75f : 0.25f;
    float wxb = 1.f - wxa;

    float v[3];
#pragma unroll
    for (int c = 0; c < 3; c++)
        v[c] = fmaf(wxa, ymix[c][xa], wxb * ymix[c][xb]);

    const float2* img2 = (const float2*)image;
    // flow scale (1, 2, 2); coords are absolute voxel coordinates
    float2 r = sample3d(img2, (float)z + v[0],
                              (float)y + 2.f * v[1],
                              (float)tx + 2.f * v[2]);

    float2* o2 = (float2*)(out + (size_t)(1 + ph) * CS);
    o2[(z * Hh + y) * Ww + tx] = r;
}

// ---------------------------------------------------------------------------
extern "C" void kernel_launch(void* const* d_in, const int* in_sizes, int n_in,
                              void* d_out, int out_size) {
    const float* image = (const float*)d_in[0];   // (1,1,48,256,256,2) f32
    const float* mvf   = (const float*)d_in[1];   // (1,4,3,48,128,128) f32
    float* out = (float*)d_out;                   // (1,5,48,256,256,2) f32

    copy_image_kernel<<<(CS / 4 + 255) / 256, 256>>>((const float4*)image,
                                                     (float4*)out);

    dim3 grid(Hh, Dd, PHn);
    warp_kernel<<<grid, 256>>>(image, mvf, out);
}

// round 7
// speedup vs baseline: 1.5875x; 1.2831x over previous
#include <cuda_runtime.h>
#include <cuda_fp16.h>

#define Dd 48
#define Hh 256
#define Ww 256
#define DMk 48
#define HMk 128
#define WMk 128
#define PHn 4
#define CS (Dd * Hh * Ww * 2)          // 6,291,456 floats per phase slab
#define NPIX (Dd * Hh * Ww)            // 3,145,728 pixels
#define MVF_CH (DMk * HMk * WMk)       // 786,432 floats per mvf channel

// 25 MB fp16 x-pair scratch: g_pair[i][0] = half2(img[i].c0,   img[i].c1)
//                            g_pair[i][1] = half2(img[i+1].c0, img[i+1].c1)
// (x+1 clamped within the row). One aligned 8B load yields both channels
// at both x-taps.
__device__ __align__(8) __half2 g_pair[NPIX][2];

// ---------------------------------------------------------------------------
// Prep: build fp16 pair scratch AND write passthrough slab out[:,0] = image.
// Reads image once (25 MB); writes 25 MB scratch + 25 MB out. Streaming.
// ---------------------------------------------------------------------------
__global__ void __launch_bounds__(256)
prep_kernel(const float2* __restrict__ img2, float2* __restrict__ out2) {
    int i = blockIdx.x * blockDim.x + threadIdx.x;
    if (i >= NPIX) return;
    int x = i & (Ww - 1);
    float2 a = __ldg(img2 + i);
    float2 b = __ldg(img2 + i + (x < Ww - 1 ? 1 : 0));
    g_pair[i][0] = __floats2half2_rn(a.x, a.y);
    g_pair[i][1] = __floats2half2_rn(b.x, b.y);
    out2[i] = a;
}

// ---------------------------------------------------------------------------
// Trilinear grid-sample (zeros padding, absolute voxel coords) via fp16 pair
// scratch: 4 x LDG.64 (8B lanes) per sample. Weights/accumulation in fp32.
// Validity folded into per-axis weights; indices clamped so loads stay legal.
// ---------------------------------------------------------------------------
__device__ __forceinline__ float2 sample3d_h(float cz, float cy, float cx) {
    float zf = floorf(cz), yf = floorf(cy), xf = floorf(cx);
    float fz = cz - zf, fy = cy - yf, fx = cx - xf;
    int z0 = (int)zf, y0 = (int)yf, x0 = (int)xf;
    int z1 = z0 + 1, y1 = y0 + 1;

    float wz[2], wy[2];
    wz[0] = (1.f - fz) * (((unsigned)z0 < (unsigned)Dd) ? 1.f : 0.f);
    wz[1] = fz         * (((unsigned)z1 < (unsigned)Dd) ? 1.f : 0.f);
    wy[0] = (1.f - fy) * (((unsigned)y0 < (unsigned)Hh) ? 1.f : 0.f);
    wy[1] = fy         * (((unsigned)y1 < (unsigned)Hh) ? 1.f : 0.f);
    float wx0 = (1.f - fx) * (((unsigned)x0       < (unsigned)Ww) ? 1.f : 0.f);
    float wx1 = fx         * (((unsigned)(x0 + 1) < (unsigned)Ww) ? 1.f : 0.f);

    int zi[2] = {min(max(z0, 0), Dd - 1), min(max(z1, 0), Dd - 1)};
    int yi[2] = {min(max(y0, 0), Hh - 1), min(max(y1, 0), Hh - 1)};
    int xc0   = min(max(x0, 0), Ww - 1);
    bool hiOK = (x0 >= 0);   // x0 == -1: both x-taps resolve to img[0] (lo half)

    float ax = 0.f, ay = 0.f;
#pragma unroll
    for (int a = 0; a < 2; a++) {
#pragma unroll
        for (int b = 0; b < 2; b++) {
            float wzy = wz[a] * wy[b];
            // One 8B load for both corners (forced single LDG.64).
            uint2 raw = __ldg(reinterpret_cast<const uint2*>(
                                  g_pair[(zi[a] * Hh + yi[b]) * Ww + xc0]));
            __half2 hlo = *reinterpret_cast<__half2*>(&raw.x);
            __half2 hhi = *reinterpret_cast<__half2*>(&raw.y);
            float lox = __low2float(hlo), loy = __high2float(hlo);
            float hix = __low2float(hhi), hiy = __high2float(hhi);
            float c1x = hiOK ? hix : lox;
            float c1y = hiOK ? hiy : loy;
            ax = fmaf(wzy, fmaf(wx0, lox, wx1 * c1x), ax);
            ay = fmaf(wzy, fmaf(wx0, loy, wx1 * c1y), ay);
        }
    }
    return make_float2(ax, ay);
}

// ---------------------------------------------------------------------------
// Fused: on-the-fly 2x linear upsample of mvf (H,W dims; D identity; jax
// half-pixel convention, edge-clamp == JAX renormalization), flow scale
// (1,2,2), grid-sample via fp16 pair scratch, channel-last float2 store.
// Block = 256 threads = one output x-row; grid = (Hh, Dd, PHn).
// ---------------------------------------------------------------------------
__global__ void __launch_bounds__(256)
warp_kernel(const float* __restrict__ mvf, float* __restrict__ out) {
    __shared__ float ymix[3][WMk];

    int tx = threadIdx.x;      // 0..255 = output x
    int y  = blockIdx.x;       // 0..255
    int z  = blockIdx.y;       // 0..47
    int ph = blockIdx.z;       // 0..3

    // y-dim resize taps (uniform across block):
    // out[2k] = .25*in[k-1] + .75*in[k]; out[2k+1] = .75*in[k] + .25*in[k+1]
    int  yk   = y >> 1;
    bool yodd = (y & 1) != 0;
    int  ya   = yodd ? yk : (yk > 0 ? yk - 1 : 0);
    int  yb   = yodd ? (yk < HMk - 1 ? yk + 1 : HMk - 1) : yk;
    float wya = yodd ? 0.75f : 0.25f;
    float wyb = 1.f - wya;

    const float* mbase = mvf + (size_t)ph * 3 * MVF_CH + (size_t)z * HMk * WMk;
    if (tx < WMk) {
#pragma unroll
        for (int c = 0; c < 3; c++) {
            const float* rowa = mbase + (size_t)c * MVF_CH + ya * WMk;
            const float* rowb = mbase + (size_t)c * MVF_CH + yb * WMk;
            ymix[c][tx] = fmaf(wya, __ldg(rowa + tx), wyb * __ldg(rowb + tx));
        }
    }
    __syncthreads();

    // x-dim resize taps for this output x = tx
    int  k    = tx >> 1;
    bool xodd = (tx & 1) != 0;
    int  xa   = xodd ? k : (k > 0 ? k - 1 : 0);
    int  xb   = xodd ? (k < WMk - 1 ? k + 1 : WMk - 1) : k;
    float wxa = xodd ? 0.75f : 0.25f;
    float wxb = 1.f - wxa;

    float v[3];
#pragma unroll
    for (int c = 0; c < 3; c++)
        v[c] = fmaf(wxa, ymix[c][xa], wxb * ymix[c][xb]);

    // flow scale (1, 2, 2); coords are absolute voxel coordinates
    float2 r = sample3d_h((float)z + v[0],
                          (float)y + 2.f * v[1],
                          (float)tx + 2.f * v[2]);

    float2* o2 = (float2*)(out + (size_t)(1 + ph) * CS);
    o2[(z * Hh + y) * Ww + tx] = r;
}

// ---------------------------------------------------------------------------
extern "C" void kernel_launch(void* const* d_in, const int* in_sizes, int n_in,
                              void* d_out, int out_size) {
    const float* image = (const float*)d_in[0];   // (1,1,48,256,256,2) f32
    const float* mvf   = (const float*)d_in[1];   // (1,4,3,48,128,128) f32
    float* out = (float*)d_out;                   // (1,5,48,256,256,2) f32

    prep_kernel<<<(NPIX + 255) / 256, 256>>>((const float2*)image,
                                             (float2*)out);

    dim3 grid(Hh, Dd, PHn);
    warp_kernel<<<grid, 256>>>(mvf, out);
}